// round 14
// baseline (speedup 1.0000x reference)
#include <cuda_runtime.h>
#include <cuda_fp16.h>
#include <cstdint>

#define N_NODES 50000
#define N_EDGES 800000
#define FEATS   512
#define N_ELEMS (N_NODES * FEATS)
#define M_TILE  64
#define GRID_M  782                 // ceil(50000/64)
#define PAD_ROWS (GRID_M * M_TILE)  // 50048

// Scratch (device globals). Zero-initialized.
__device__ __half g_y_h [(size_t)PAD_ROWS * FEATS];  // y = dropout(x) @ W, fp16
__device__ __half g_Wt_h[(size_t)FEATS * FEATS];     // W^T fp16: Wt[n][k]
__device__ int    g_rowptr[N_NODES + 1];

// ---------------------------------------------------------------------------
// helpers
// ---------------------------------------------------------------------------
__device__ __forceinline__ uint32_t smem_u32(const void* p) {
    uint32_t a;
    asm("{ .reg .u64 t; cvta.to.shared.u64 t, %1; cvt.u32.u64 %0, t; }" : "=r"(a) : "l"(p));
    return a;
}
__device__ __forceinline__ void cp_async16(uint32_t dst, const void* src) {
    asm volatile("cp.async.cg.shared.global [%0], [%1], 16;" :: "r"(dst), "l"(src));
}
__device__ __forceinline__ void cp_commit() {
    asm volatile("cp.async.commit_group;" ::: "memory");
}
template <int N>
__device__ __forceinline__ void cp_wait() {
    asm volatile("cp.async.wait_group %0;" :: "n"(N) : "memory");
}
__device__ __forceinline__ void mma_f16(float* c, const uint32_t* a, const uint32_t* b) {
    asm volatile(
        "mma.sync.aligned.m16n8k16.row.col.f32.f16.f16.f32 "
        "{%0,%1,%2,%3}, {%4,%5,%6,%7}, {%8,%9}, {%0,%1,%2,%3};"
        : "+f"(c[0]), "+f"(c[1]), "+f"(c[2]), "+f"(c[3])
        : "r"(a[0]), "r"(a[1]), "r"(a[2]), "r"(a[3]), "r"(b[0]), "r"(b[1]));
}
__device__ __forceinline__ void ldsm_x4(uint32_t& r0, uint32_t& r1, uint32_t& r2,
                                        uint32_t& r3, uint32_t addr) {
    asm volatile("ldmatrix.sync.aligned.m8n8.x4.shared.b16 {%0,%1,%2,%3}, [%4];"
                 : "=r"(r0), "=r"(r1), "=r"(r2), "=r"(r3) : "r"(addr));
}

// ---------------------------------------------------------------------------
// Kernel 0a: Wt[n][k] = (fp16) W[k][n]
// ---------------------------------------------------------------------------
__global__ void transpose_W_kernel(const float* __restrict__ W) {
    __shared__ float t[32][33];
    const int tx = threadIdx.x, ty = threadIdx.y;          // 32 x 8
    const int bx = blockIdx.x, by = blockIdx.y;
    const int x = bx * 32 + tx;
#pragma unroll
    for (int i = 0; i < 4; i++) {
        const int y = by * 32 + ty + i * 8;
        t[ty + i * 8][tx] = W[(size_t)y * 512 + x];
    }
    __syncthreads();
    const int x2 = by * 32 + tx;                           // k
#pragma unroll
    for (int i = 0; i < 4; i++) {
        const int y2 = bx * 32 + ty + i * 8;               // n
        g_Wt_h[(size_t)y2 * 512 + x2] = __float2half_rn(t[tx][ty + i * 8]);
    }
}

// ---------------------------------------------------------------------------
// Kernel 0b: row_ptr from sorted edge_dst.
// ---------------------------------------------------------------------------
__global__ void rowptr_kernel(const int* __restrict__ edge_dst) {
    const int e = blockIdx.x * blockDim.x + threadIdx.x;
    if (e > N_EDGES) return;
    const int d_prev = (e == 0)       ? -1      : edge_dst[e - 1];
    const int d_cur  = (e == N_EDGES) ? N_NODES : edge_dst[e];
    for (int n = d_prev + 1; n <= d_cur; n++) g_rowptr[n] = e;
}

// ---------------------------------------------------------------------------
// threefry-2x32-20, JAX partitionable stream. keep <=> bits < 0xE6666600.
// ---------------------------------------------------------------------------
__device__ __forceinline__ unsigned rotl32(unsigned x, int d) {
    return (x << d) | (x >> (32 - d));
}
__device__ __forceinline__ unsigned threefry_elem(unsigned i) {
    const unsigned ks0 = 0u, ks1 = 42u;
    const unsigned ks2 = ks0 ^ ks1 ^ 0x1BD11BDAu;
    unsigned x0 = 0u, x1 = i;
    x0 += ks0; x1 += ks1;
#define TF_ROUND(r) { x0 += x1; x1 = rotl32(x1, (r)); x1 ^= x0; }
    TF_ROUND(13) TF_ROUND(15) TF_ROUND(26) TF_ROUND(6)
    x0 += ks1; x1 += ks2 + 1u;
    TF_ROUND(17) TF_ROUND(29) TF_ROUND(16) TF_ROUND(24)
    x0 += ks2; x1 += ks0 + 2u;
    TF_ROUND(13) TF_ROUND(15) TF_ROUND(26) TF_ROUND(6)
    x0 += ks0; x1 += ks1 + 3u;
    TF_ROUND(17) TF_ROUND(29) TF_ROUND(16) TF_ROUND(24)
    x0 += ks1; x1 += ks2 + 4u;
    TF_ROUND(13) TF_ROUND(15) TF_ROUND(26) TF_ROUND(6)
    x0 += ks2; x1 += ks0 + 5u;
#undef TF_ROUND
    return x0 ^ x1;
}

// ---------------------------------------------------------------------------
// Kernel 1 (FUSED): y = dropout(x) @ W. One CTA = 64 M-rows x full N=512.
// A tile (64x512 fp16, dropout applied on the fly) lives in smem for the
// whole kernel; threefry runs once per element on the ALU pipe while HMMA
// runs on the tensor pipe. B (Wt) double-buffered via cp.async, 32 steps
// (4 N-blocks x 8 K-chunks). Proven R11 ldsm/mma fragment templates.
// ---------------------------------------------------------------------------
#define A_LDH   520                       // halves per A row (1040 B, 4-bank step)
#define A_BYTES (64 * A_LDH * 2)          // 66560
#define B_LDH   72                        // halves per B row (144 B)
#define B_STAGE (128 * B_LDH * 2)         // 18432
#define FUSED_SMEM (A_BYTES + 2 * B_STAGE)   // 103424

__global__ void __launch_bounds__(256, 2)
fused_dropout_gemm(const float* __restrict__ x) {
    extern __shared__ __half smh[];
    const uint32_t aBase = smem_u32(smh);
    const uint32_t bBase = aBase + A_BYTES;

    const int tid   = threadIdx.x;
    const int wid   = tid >> 5;
    const int lane  = tid & 31;
    const int warpM = wid & 1;           // M offset 0/32
    const int warpN = wid >> 1;          // 0..3 -> 32-col block within N-block
    const int m0 = blockIdx.x * M_TILE;

    // B chunk loader: (nb, kc) -> stage st. 128 n-rows x 64 halves.
    auto loadB = [&](int st, int nb, int kc) {
#pragma unroll
        for (int it = 0; it < 4; it++) {
            const int idx = it * 256 + tid;
            const int row = idx >> 3, seg = idx & 7;
            cp_async16(bBase + st * B_STAGE + row * 144 + seg * 16,
                       g_Wt_h + (size_t)(nb * 128 + row) * 512 + kc * 64 + seg * 8);
        }
        cp_commit();
    };
    loadB(0, 0, 0);

    // ---- A fill: load x fp32, threefry dropout, convert fp16, STS ----
    const unsigned THR = 0xE6666600u;    // 7549747 << 9 : exact u < 0.9f
    const float inv_keep = 1.0f / 0.9f;
#pragma unroll 1
    for (int it = 0; it < 32; it++) {
        const int fidx = it * 256 + tid;       // float4 index 0..8191
        const int row  = fidx >> 7;            // 0..63
        const int c4   = fidx & 127;
        const int grow = m0 + row;
        uint2 pack = make_uint2(0u, 0u);
        if (grow < N_NODES) {
            const float4 v = __ldcs(reinterpret_cast<const float4*>(
                                        x + (size_t)grow * 512 + c4 * 4));
            const unsigned i0 = (unsigned)(grow * 512 + c4 * 4);
            const unsigned b0 = threefry_elem(i0 + 0u);
            const unsigned b1 = threefry_elem(i0 + 1u);
            const unsigned b2 = threefry_elem(i0 + 2u);
            const unsigned b3 = threefry_elem(i0 + 3u);
            const float o0 = (b0 < THR) ? v.x * inv_keep : 0.0f;
            const float o1 = (b1 < THR) ? v.y * inv_keep : 0.0f;
            const float o2 = (b2 < THR) ? v.z * inv_keep : 0.0f;
            const float o3 = (b3 < THR) ? v.w * inv_keep : 0.0f;
            const __half2 h01 = __floats2half2_rn(o0, o1);
            const __half2 h23 = __floats2half2_rn(o2, o3);
            pack.x = *reinterpret_cast<const uint32_t*>(&h01);
            pack.y = *reinterpret_cast<const uint32_t*>(&h23);
        }
        *reinterpret_cast<uint2*>(
            reinterpret_cast<char*>(smh) + (size_t)(row * A_LDH + c4 * 4) * 2) = pack;
    }

    // ---- fragment address templates (R11-proven) ----
    const int rA = warpM * 32 + (lane & 15);
    const uint32_t aLane = (uint32_t)(rA * A_LDH + ((lane & 16) ? 8 : 0)) * 2;
    const int rB = warpN * 32 + (lane & 7) + ((lane & 16) >> 1);
    const uint32_t bLane = (uint32_t)(rB * B_LDH + ((lane & 8) ? 8 : 0)) * 2;

    float acc[2][4][4];
#pragma unroll
    for (int i = 0; i < 2; i++)
#pragma unroll
        for (int j = 0; j < 4; j++)
#pragma unroll
            for (int r = 0; r < 4; r++) acc[i][j][r] = 0.f;

    const int qrow = lane >> 2;
    const int qcol = lane & 3;

    // ---- main loop: 32 steps = 4 N-blocks x 8 K-chunks ----
#pragma unroll 1
    for (int s = 0; s < 32; s++) {
        const int st = s & 1;
        const int nb = s >> 3, kc = s & 7;
        cp_wait<0>();                   // B(s) complete (this thread)
        __syncthreads();                // B(s) visible; prior mma on st^1 done
        if (s + 1 < 32) loadB(st ^ 1, (s + 1) >> 3, (s + 1) & 7);

        const uint32_t aCol = (uint32_t)(kc * 64) * 2;
        const uint32_t bStage = bBase + st * B_STAGE + bLane;
#pragma unroll
        for (int kk = 0; kk < 4; kk++) {
            const uint32_t kOff = kk * 32;          // 16 halves
            uint32_t af[2][4];
#pragma unroll
            for (int mt = 0; mt < 2; mt++)
                ldsm_x4(af[mt][0], af[mt][1], af[mt][2], af[mt][3],
                        aBase + aLane + aCol + (uint32_t)(mt * 16 * A_LDH) * 2 + kOff);
            uint32_t bf[4][2];
#pragma unroll
            for (int ntp = 0; ntp < 2; ntp++)
                ldsm_x4(bf[2 * ntp][0], bf[2 * ntp][1],
                        bf[2 * ntp + 1][0], bf[2 * ntp + 1][1],
                        bStage + (uint32_t)(ntp * 16 * B_LDH) * 2 + kOff);
#pragma unroll
            for (int mt = 0; mt < 2; mt++)
#pragma unroll
                for (int nt = 0; nt < 4; nt++)
                    mma_f16(acc[mt][nt], af[mt], bf[nt]);
        }

        if ((s & 7) == 7) {
            // epilogue for this N-block: y fp16 streaming stores
#pragma unroll
            for (int mt = 0; mt < 2; mt++) {
                const int row0 = m0 + warpM * 32 + mt * 16 + qrow;
                const int row1 = row0 + 8;
#pragma unroll
                for (int nt = 0; nt < 4; nt++) {
                    const int col = nb * 128 + warpN * 32 + nt * 8 + 2 * qcol;
                    const __half2 p0 = __floats2half2_rn(acc[mt][nt][0], acc[mt][nt][1]);
                    const __half2 p1 = __floats2half2_rn(acc[mt][nt][2], acc[mt][nt][3]);
                    __stcs(reinterpret_cast<uint32_t*>(g_y_h + (size_t)row0 * 512 + col),
                           *reinterpret_cast<const uint32_t*>(&p0));
                    __stcs(reinterpret_cast<uint32_t*>(g_y_h + (size_t)row1 * 512 + col),
                           *reinterpret_cast<const uint32_t*>(&p1));
#pragma unroll
                    for (int r = 0; r < 4; r++) acc[mt][nt][r] = 0.f;
                }
            }
        }
    }
}

// ---------------------------------------------------------------------------
// Kernel 2 (FUSED): out[n] = relu(segsum(w_e * y[src_e]) + b). Final output.
// Same gather structure as the proven agg kernel; fp32 accumulate.
// ---------------------------------------------------------------------------
__global__ void agg_out_kernel(const float* __restrict__ edge_w,
                               const int*   __restrict__ edge_src,
                               const float* __restrict__ bias,
                               float* __restrict__ out) {
    const int node = blockIdx.x;
    const int start = g_rowptr[node];
    const int end   = g_rowptr[node + 1];

    const int f = threadIdx.x;  // 0..127, owns feats [4f, 4f+4)
    float4 acc = make_float4(0.f, 0.f, 0.f, 0.f);

    int e = start;
#pragma unroll 1
    for (; e + 4 <= end; e += 4) {
        const float w0 = edge_w[e + 0], w1 = edge_w[e + 1];
        const float w2 = edge_w[e + 2], w3 = edge_w[e + 3];
        const int   s0 = edge_src[e + 0], s1 = edge_src[e + 1];
        const int   s2 = edge_src[e + 2], s3 = edge_src[e + 3];
        const uint2 r0 = reinterpret_cast<const uint2*>(g_y_h + (size_t)s0 * FEATS)[f];
        const uint2 r1 = reinterpret_cast<const uint2*>(g_y_h + (size_t)s1 * FEATS)[f];
        const uint2 r2 = reinterpret_cast<const uint2*>(g_y_h + (size_t)s2 * FEATS)[f];
        const uint2 r3 = reinterpret_cast<const uint2*>(g_y_h + (size_t)s3 * FEATS)[f];
#define ACC_EDGE(rr, ww) { \
        const float2 lo = __half22float2(*reinterpret_cast<const __half2*>(&(rr).x)); \
        const float2 hi = __half22float2(*reinterpret_cast<const __half2*>(&(rr).y)); \
        acc.x += (ww) * lo.x; acc.y += (ww) * lo.y; \
        acc.z += (ww) * hi.x; acc.w += (ww) * hi.y; }
        ACC_EDGE(r0, w0) ACC_EDGE(r1, w1) ACC_EDGE(r2, w2) ACC_EDGE(r3, w3)
    }
#pragma unroll 1
    for (; e < end; e++) {
        const float w = edge_w[e];
        const int   s = edge_src[e];
        const uint2 rr = reinterpret_cast<const uint2*>(g_y_h + (size_t)s * FEATS)[f];
        ACC_EDGE(rr, w)
    }
#undef ACC_EDGE
    const float4 bv = *reinterpret_cast<const float4*>(bias + (f << 2));
    float4 o;
    o.x = fmaxf(acc.x + bv.x, 0.f);
    o.y = fmaxf(acc.y + bv.y, 0.f);
    o.z = fmaxf(acc.z + bv.z, 0.f);
    o.w = fmaxf(acc.w + bv.w, 0.f);
    __stcs(reinterpret_cast<float4*>(out + (size_t)node * 512) + f, o);
}

// ---------------------------------------------------------------------------
// Launch:
//   stream0: transpose_W -> fused_dropout_gemm -> (wait rowptr) -> agg_out
//   s1:      rowptr (parallel with the above)
// ---------------------------------------------------------------------------
extern "C" void kernel_launch(void* const* d_in, const int* in_sizes, int n_in,
                              void* d_out, int out_size) {
    const float* x        = (const float*)d_in[0];
    const float* edge_w   = (const float*)d_in[1];
    const float* W        = (const float*)d_in[2];
    const float* b        = (const float*)d_in[3];
    const int*   edge_src = (const int*)  d_in[4];
    const int*   edge_dst = (const int*)  d_in[5];
    float* out = (float*)d_out;

    static cudaStream_t s1 = nullptr;
    static cudaEvent_t evStart, evR;
    if (s1 == nullptr) {
        cudaStreamCreateWithFlags(&s1, cudaStreamNonBlocking);
        cudaEventCreateWithFlags(&evStart, cudaEventDisableTiming);
        cudaEventCreateWithFlags(&evR,     cudaEventDisableTiming);
        cudaFuncSetAttribute(fused_dropout_gemm,
                             cudaFuncAttributeMaxDynamicSharedMemorySize,
                             FUSED_SMEM);
    }

    cudaEventRecord(evStart, 0);
    cudaStreamWaitEvent(s1, evStart, 0);
    rowptr_kernel<<<(N_EDGES + 256) / 256, 256, 0, s1>>>(edge_dst);
    cudaEventRecord(evR, s1);

    transpose_W_kernel<<<dim3(16, 16), dim3(32, 8), 0, 0>>>(W);
    fused_dropout_gemm<<<GRID_M, 256, FUSED_SMEM, 0>>>(x);
    cudaStreamWaitEvent(0, evR, 0);
    agg_out_kernel<<<N_NODES, 128, 0, 0>>>(edge_w, edge_src, b, out);
}

// round 15
// speedup vs baseline: 1.0964x; 1.0964x over previous
#include <cuda_runtime.h>
#include <cuda_fp16.h>
#include <cstdint>

#define N_NODES 50000
#define N_EDGES 800000
#define FEATS   512
#define N_ELEMS (N_NODES * FEATS)
#define M_TILES 391                 // ceil(50000/128)
#define PAD_ROWS (M_TILES * 128)    // 50048

// Scratch (device globals). Zero-initialized; pad rows of g_agg_h stay zero.
__device__ __half g_xd_h [(size_t)N_NODES * FEATS];   // fp16 dropout output
__device__ __half g_agg_h[(size_t)PAD_ROWS * FEATS];  // fp16 agg output
__device__ __half g_Wt_h [(size_t)FEATS * FEATS];     // W^T fp16: Wt[n][k]
__device__ int    g_rowptr[N_NODES + 1];

// ---------------------------------------------------------------------------
// helpers
// ---------------------------------------------------------------------------
__device__ __forceinline__ uint32_t smem_u32(const void* p) {
    uint32_t a;
    asm("{ .reg .u64 t; cvta.to.shared.u64 t, %1; cvt.u32.u64 %0, t; }" : "=r"(a) : "l"(p));
    return a;
}
__device__ __forceinline__ void cp_async16(uint32_t dst, const void* src) {
    asm volatile("cp.async.cg.shared.global [%0], [%1], 16;" :: "r"(dst), "l"(src));
}
__device__ __forceinline__ void cp_commit() {
    asm volatile("cp.async.commit_group;" ::: "memory");
}
template <int N>
__device__ __forceinline__ void cp_wait() {
    asm volatile("cp.async.wait_group %0;" :: "n"(N) : "memory");
}
// D(16x8 f32) += A(16x16 f16, row) * B(16x8 f16, col)
__device__ __forceinline__ void mma_f16(float* c, const uint32_t* a, const uint32_t* b) {
    asm volatile(
        "mma.sync.aligned.m16n8k16.row.col.f32.f16.f16.f32 "
        "{%0,%1,%2,%3}, {%4,%5,%6,%7}, {%8,%9}, {%0,%1,%2,%3};"
        : "+f"(c[0]), "+f"(c[1]), "+f"(c[2]), "+f"(c[3])
        : "r"(a[0]), "r"(a[1]), "r"(a[2]), "r"(a[3]), "r"(b[0]), "r"(b[1]));
}
__device__ __forceinline__ void ldsm_x4(uint32_t& r0, uint32_t& r1, uint32_t& r2,
                                        uint32_t& r3, uint32_t addr) {
    asm volatile("ldmatrix.sync.aligned.m8n8.x4.shared.b16 {%0,%1,%2,%3}, [%4];"
                 : "=r"(r0), "=r"(r1), "=r"(r2), "=r"(r3) : "r"(addr));
}

// ---------------------------------------------------------------------------
// Kernel 0a: Wt[n][k] = (fp16) W[k][n]
// ---------------------------------------------------------------------------
__global__ void transpose_W_kernel(const float* __restrict__ W) {
    __shared__ float t[32][33];
    const int tx = threadIdx.x, ty = threadIdx.y;          // 32 x 8
    const int bx = blockIdx.x, by = blockIdx.y;
    const int x = bx * 32 + tx;
#pragma unroll
    for (int i = 0; i < 4; i++) {
        const int y = by * 32 + ty + i * 8;
        t[ty + i * 8][tx] = W[(size_t)y * 512 + x];
    }
    __syncthreads();
    const int x2 = by * 32 + tx;                           // k
#pragma unroll
    for (int i = 0; i < 4; i++) {
        const int y2 = bx * 32 + ty + i * 8;               // n
        g_Wt_h[(size_t)y2 * 512 + x2] = __float2half_rn(t[tx][ty + i * 8]);
    }
}

// ---------------------------------------------------------------------------
// Kernel 0b: row_ptr from sorted edge_dst.
// ---------------------------------------------------------------------------
__global__ void rowptr_kernel(const int* __restrict__ edge_dst) {
    const int e = blockIdx.x * blockDim.x + threadIdx.x;
    if (e > N_EDGES) return;
    const int d_prev = (e == 0)       ? -1      : edge_dst[e - 1];
    const int d_cur  = (e == N_EDGES) ? N_NODES : edge_dst[e];
    for (int n = d_prev + 1; n <= d_cur; n++) g_rowptr[n] = e;
}

// ---------------------------------------------------------------------------
// Kernel 1: dropout, JAX partitionable threefry-2x32-20; fp16 output.
// keep <=> bits < 0xE6666600 (== 7549747<<9; exact integer form of u < 0.9f).
// 8 elements per thread.
// ---------------------------------------------------------------------------
__device__ __forceinline__ unsigned rotl32(unsigned x, int d) {
    return (x << d) | (x >> (32 - d));
}
__device__ __forceinline__ unsigned threefry_elem(unsigned i) {
    const unsigned ks0 = 0u, ks1 = 42u;
    const unsigned ks2 = ks0 ^ ks1 ^ 0x1BD11BDAu;
    unsigned x0 = 0u, x1 = i;
    x0 += ks0; x1 += ks1;
#define TF_ROUND(r) { x0 += x1; x1 = rotl32(x1, (r)); x1 ^= x0; }
    TF_ROUND(13) TF_ROUND(15) TF_ROUND(26) TF_ROUND(6)
    x0 += ks1; x1 += ks2 + 1u;
    TF_ROUND(17) TF_ROUND(29) TF_ROUND(16) TF_ROUND(24)
    x0 += ks2; x1 += ks0 + 2u;
    TF_ROUND(13) TF_ROUND(15) TF_ROUND(26) TF_ROUND(6)
    x0 += ks0; x1 += ks1 + 3u;
    TF_ROUND(17) TF_ROUND(29) TF_ROUND(16) TF_ROUND(24)
    x0 += ks1; x1 += ks2 + 4u;
    TF_ROUND(13) TF_ROUND(15) TF_ROUND(26) TF_ROUND(6)
    x0 += ks2; x1 += ks0 + 5u;
#undef TF_ROUND
    return x0 ^ x1;
}

__global__ void dropout_kernel(const float* __restrict__ x) {
    const unsigned base = (blockIdx.x * blockDim.x + threadIdx.x) * 8u;
    if (base >= (unsigned)N_ELEMS) return;
    const float4 va = __ldcs(reinterpret_cast<const float4*>(x + base));
    const float4 vb = __ldcs(reinterpret_cast<const float4*>(x + base + 4));
    const float inv_keep = 1.0f / 0.9f;
    const unsigned THR = 0xE6666600u;

    float o[8];
    const float vi[8] = { va.x, va.y, va.z, va.w, vb.x, vb.y, vb.z, vb.w };
#pragma unroll
    for (int j = 0; j < 8; j++) {
        const unsigned bj = threefry_elem(base + (unsigned)j);
        o[j] = (bj < THR) ? vi[j] * inv_keep : 0.0f;
    }
    uint4 pack;
    const __half2 h0 = __floats2half2_rn(o[0], o[1]);
    const __half2 h1 = __floats2half2_rn(o[2], o[3]);
    const __half2 h2 = __floats2half2_rn(o[4], o[5]);
    const __half2 h3 = __floats2half2_rn(o[6], o[7]);
    pack.x = *reinterpret_cast<const uint32_t*>(&h0);
    pack.y = *reinterpret_cast<const uint32_t*>(&h1);
    pack.z = *reinterpret_cast<const uint32_t*>(&h2);
    pack.w = *reinterpret_cast<const uint32_t*>(&h3);
    *reinterpret_cast<uint4*>(g_xd_h + base) = pack;
}

// ---------------------------------------------------------------------------
// Kernel 2: segment-sum aggregation over fp16 xd; fp32 accumulate; fp16 out.
// Monolithic, unroll x4, streaming result store. (Measured optimum.)
// ---------------------------------------------------------------------------
__global__ void agg_kernel(const float* __restrict__ edge_w,
                           const int*   __restrict__ edge_src) {
    const int node = blockIdx.x;
    const int start = g_rowptr[node];
    const int end   = g_rowptr[node + 1];

    const int f = threadIdx.x;  // 0..127, owns feats [4f, 4f+4)
    float4 acc = make_float4(0.f, 0.f, 0.f, 0.f);

    int e = start;
#pragma unroll 1
    for (; e + 4 <= end; e += 4) {
        const float w0 = edge_w[e + 0], w1 = edge_w[e + 1];
        const float w2 = edge_w[e + 2], w3 = edge_w[e + 3];
        const int   s0 = edge_src[e + 0], s1 = edge_src[e + 1];
        const int   s2 = edge_src[e + 2], s3 = edge_src[e + 3];
        const uint2 r0 = reinterpret_cast<const uint2*>(g_xd_h + (size_t)s0 * FEATS)[f];
        const uint2 r1 = reinterpret_cast<const uint2*>(g_xd_h + (size_t)s1 * FEATS)[f];
        const uint2 r2 = reinterpret_cast<const uint2*>(g_xd_h + (size_t)s2 * FEATS)[f];
        const uint2 r3 = reinterpret_cast<const uint2*>(g_xd_h + (size_t)s3 * FEATS)[f];
#define ACC_EDGE(rr, ww) { \
        const float2 lo = __half22float2(*reinterpret_cast<const __half2*>(&(rr).x)); \
        const float2 hi = __half22float2(*reinterpret_cast<const __half2*>(&(rr).y)); \
        acc.x += (ww) * lo.x; acc.y += (ww) * lo.y; \
        acc.z += (ww) * hi.x; acc.w += (ww) * hi.y; }
        ACC_EDGE(r0, w0) ACC_EDGE(r1, w1) ACC_EDGE(r2, w2) ACC_EDGE(r3, w3)
    }
#pragma unroll 1
    for (; e < end; e++) {
        const float w = edge_w[e];
        const int   s = edge_src[e];
        const uint2 rr = reinterpret_cast<const uint2*>(g_xd_h + (size_t)s * FEATS)[f];
        ACC_EDGE(rr, w)
    }
#undef ACC_EDGE
    const __half2 h01 = __floats2half2_rn(acc.x, acc.y);
    const __half2 h23 = __floats2half2_rn(acc.z, acc.w);
    uint2 pack;
    pack.x = *reinterpret_cast<const uint32_t*>(&h01);
    pack.y = *reinterpret_cast<const uint32_t*>(&h23);
    __stcs(reinterpret_cast<uint2*>(g_agg_h + (size_t)node * FEATS) + f, pack);
}

// ---------------------------------------------------------------------------
// Kernel 3: fp16 mma.sync m16n8k16 GEMM, fp32 accum, ldmatrix fragments.
// 128x128 CTA tile, 8 warps (64x32 warp tiles), BK=64 halves, 2-stage
// cp.async, smem rows 144 B. (R11 measured-best configuration.)
// ---------------------------------------------------------------------------
#define BKH 64                          // halves per K chunk
#define LDH 72                          // padded halves per row (144 B)
#define STAGE_H (128 * LDH)             // halves per stage per matrix
#define GEMM_SMEM_BYTES (4 * STAGE_H * 2)   // A0,A1,B0,B1 = 73728 B

__global__ void __launch_bounds__(256, 2)
gemm_mma_kernel(const float* __restrict__ bias, float* __restrict__ out) {
    extern __shared__ __half smh[];
    __half* Asm = smh;                  // [2][128][LDH]
    __half* Bsm = smh + 2 * STAGE_H;    // [2][128][LDH]

    const int tid   = threadIdx.x;
    const int wid   = tid >> 5;
    const int lane  = tid & 31;
    const int warpM = wid & 1;          // M offset 0/64
    const int warpN = wid >> 1;         // 0..3 -> N offset 0/32/64/96
    const int m0 = blockIdx.y * 128;
    const int n0 = blockIdx.x * 128;

    const uint32_t aBase = smem_u32(Asm);
    const uint32_t bBase = smem_u32(Bsm);
    const uint32_t stageBytes = STAGE_H * 2;

    const int rA   = warpM * 64 + (lane & 15);
    const int kAh  = (lane & 16) ? 8 : 0;
    const uint32_t aLane = (uint32_t)(rA * LDH + kAh) * 2;
    const int rB   = warpN * 32 + (lane & 7) + ((lane & 16) >> 1);
    const int kBh  = (lane & 8) ? 8 : 0;
    const uint32_t bLane = (uint32_t)(rB * LDH + kBh) * 2;

    float acc[4][4][4];
#pragma unroll
    for (int i = 0; i < 4; i++)
#pragma unroll
        for (int j = 0; j < 4; j++)
#pragma unroll
            for (int r = 0; r < 4; r++) acc[i][j][r] = 0.f;

    auto load_tile = [&](int s, int k0) {
#pragma unroll
        for (int it = 0; it < 4; it++) {
            const int idx = it * 256 + tid;            // 0..1023
            const int row = idx >> 3, seg = idx & 7;
            cp_async16(aBase + s * stageBytes + row * 144 + seg * 16,
                       g_agg_h + (size_t)(m0 + row) * 512 + k0 + seg * 8);
        }
#pragma unroll
        for (int it = 0; it < 4; it++) {
            const int idx = it * 256 + tid;
            const int row = idx >> 3, seg = idx & 7;
            cp_async16(bBase + s * stageBytes + row * 144 + seg * 16,
                       g_Wt_h + (size_t)(n0 + row) * 512 + k0 + seg * 8);
        }
        cp_commit();
    };

    load_tile(0, 0);

    for (int c = 0; c < 8; c++) {
        const int s = c & 1;
        cp_wait<0>();
        __syncthreads();
        if (c + 1 < 8) load_tile(s ^ 1, (c + 1) * BKH);   // overlaps mma below

        const uint32_t aStage = aBase + s * stageBytes + aLane;
        const uint32_t bStage = bBase + s * stageBytes + bLane;
#pragma unroll
        for (int kk = 0; kk < 4; kk++) {
            const uint32_t kOff = kk * 32;                // 16 halves = 32 B
            uint32_t af[4][4];
#pragma unroll
            for (int mt = 0; mt < 4; mt++)
                ldsm_x4(af[mt][0], af[mt][1], af[mt][2], af[mt][3],
                        aStage + (uint32_t)(mt * 16 * LDH) * 2 + kOff);
            uint32_t bf[4][2];
#pragma unroll
            for (int ntp = 0; ntp < 2; ntp++)
                ldsm_x4(bf[2 * ntp][0], bf[2 * ntp][1],
                        bf[2 * ntp + 1][0], bf[2 * ntp + 1][1],
                        bStage + (uint32_t)(ntp * 16 * LDH) * 2 + kOff);
#pragma unroll
            for (int mt = 0; mt < 4; mt++)
#pragma unroll
                for (int nt = 0; nt < 4; nt++)
                    mma_f16(acc[mt][nt], af[mt], bf[nt]);
        }
    }

    const int qrow = lane >> 2;
    const int qcol = lane & 3;

    // epilogue: bias + relu, streaming stores
#pragma unroll
    for (int mt = 0; mt < 4; mt++) {
        const int row0 = m0 + warpM * 64 + mt * 16 + qrow;
        const int row1 = row0 + 8;
#pragma unroll
        for (int nt = 0; nt < 4; nt++) {
            const int col = n0 + warpN * 32 + nt * 8 + 2 * qcol;
            const float b0 = __ldg(bias + col);
            const float b1 = __ldg(bias + col + 1);
            if (row0 < N_NODES) {
                float2 o;
                o.x = fmaxf(acc[mt][nt][0] + b0, 0.f);
                o.y = fmaxf(acc[mt][nt][1] + b1, 0.f);
                __stcs(reinterpret_cast<float2*>(out + (size_t)row0 * 512 + col), o);
            }
            if (row1 < N_NODES) {
                float2 o;
                o.x = fmaxf(acc[mt][nt][2] + b0, 0.f);
                o.y = fmaxf(acc[mt][nt][3] + b1, 0.f);
                __stcs(reinterpret_cast<float2*>(out + (size_t)row1 * 512 + col), o);
            }
        }
    }
}

// ---------------------------------------------------------------------------
// Launch: serial core (measured optimum); aux forked under dropout (free).
// ---------------------------------------------------------------------------
extern "C" void kernel_launch(void* const* d_in, const int* in_sizes, int n_in,
                              void* d_out, int out_size) {
    const float* x        = (const float*)d_in[0];
    const float* edge_w   = (const float*)d_in[1];
    const float* W        = (const float*)d_in[2];
    const float* b        = (const float*)d_in[3];
    const int*   edge_src = (const int*)  d_in[4];
    const int*   edge_dst = (const int*)  d_in[5];
    float* out = (float*)d_out;

    static cudaStream_t s1 = nullptr;
    static cudaEvent_t evStart, evAux;
    if (s1 == nullptr) {
        cudaStreamCreateWithFlags(&s1, cudaStreamNonBlocking);
        cudaEventCreateWithFlags(&evStart, cudaEventDisableTiming);
        cudaEventCreateWithFlags(&evAux,   cudaEventDisableTiming);
        cudaFuncSetAttribute(gemm_mma_kernel,
                             cudaFuncAttributeMaxDynamicSharedMemorySize,
                             GEMM_SMEM_BYTES);
    }

    cudaEventRecord(evStart, 0);
    cudaStreamWaitEvent(s1, evStart, 0);
    transpose_W_kernel<<<dim3(16, 16), dim3(32, 8), 0, s1>>>(W);
    rowptr_kernel<<<(N_EDGES + 256) / 256, 256, 0, s1>>>(edge_dst);
    cudaEventRecord(evAux, s1);

    dropout_kernel<<<(N_ELEMS / 8 + 255) / 256, 256, 0, 0>>>(x);

    cudaStreamWaitEvent(0, evAux, 0);
    agg_kernel<<<N_NODES, 128, 0, 0>>>(edge_w, edge_src);
    gemm_mma_kernel<<<dim3(4, M_TILES), 256, GEMM_SMEM_BYTES, 0>>>(b, out);
}

// round 16
// speedup vs baseline: 1.1198x; 1.0214x over previous
#include <cuda_runtime.h>
#include <cuda_fp16.h>
#include <cstdint>

#define N_NODES 50000
#define N_EDGES 800000
#define FEATS   512
#define N_ELEMS (N_NODES * FEATS)
#define M_TILES 391                 // ceil(50000/128)
#define PAD_ROWS (M_TILES * 128)    // 50048

// Scratch (device globals). Zero-initialized; pad rows of g_agg_h stay zero.
__device__ __half g_xd_h [(size_t)N_NODES * FEATS];   // fp16 dropout output
__device__ __half g_agg_h[(size_t)PAD_ROWS * FEATS];  // fp16 agg output
__device__ __half g_Wt_h [(size_t)FEATS * FEATS];     // W^T fp16: Wt[n][k]
__device__ int    g_rowptr[N_NODES + 1];

// ---------------------------------------------------------------------------
// helpers
// ---------------------------------------------------------------------------
__device__ __forceinline__ uint32_t smem_u32(const void* p) {
    uint32_t a;
    asm("{ .reg .u64 t; cvta.to.shared.u64 t, %1; cvt.u32.u64 %0, t; }" : "=r"(a) : "l"(p));
    return a;
}
__device__ __forceinline__ void cp_async16(uint32_t dst, const void* src) {
    asm volatile("cp.async.cg.shared.global [%0], [%1], 16;" :: "r"(dst), "l"(src));
}
__device__ __forceinline__ void cp_commit() {
    asm volatile("cp.async.commit_group;" ::: "memory");
}
template <int N>
__device__ __forceinline__ void cp_wait() {
    asm volatile("cp.async.wait_group %0;" :: "n"(N) : "memory");
}
// D(16x8 f32) += A(16x16 f16, row) * B(16x8 f16, col)
__device__ __forceinline__ void mma_f16(float* c, const uint32_t* a, const uint32_t* b) {
    asm volatile(
        "mma.sync.aligned.m16n8k16.row.col.f32.f16.f16.f32 "
        "{%0,%1,%2,%3}, {%4,%5,%6,%7}, {%8,%9}, {%0,%1,%2,%3};"
        : "+f"(c[0]), "+f"(c[1]), "+f"(c[2]), "+f"(c[3])
        : "r"(a[0]), "r"(a[1]), "r"(a[2]), "r"(a[3]), "r"(b[0]), "r"(b[1]));
}
__device__ __forceinline__ void ldsm_x4(uint32_t& r0, uint32_t& r1, uint32_t& r2,
                                        uint32_t& r3, uint32_t addr) {
    asm volatile("ldmatrix.sync.aligned.m8n8.x4.shared.b16 {%0,%1,%2,%3}, [%4];"
                 : "=r"(r0), "=r"(r1), "=r"(r2), "=r"(r3) : "r"(addr));
}

// ---------------------------------------------------------------------------
// Kernel 0a: Wt[n][k] = (fp16) W[k][n]
// ---------------------------------------------------------------------------
__global__ void transpose_W_kernel(const float* __restrict__ W) {
    __shared__ float t[32][33];
    const int tx = threadIdx.x, ty = threadIdx.y;          // 32 x 8
    const int bx = blockIdx.x, by = blockIdx.y;
    const int x = bx * 32 + tx;
#pragma unroll
    for (int i = 0; i < 4; i++) {
        const int y = by * 32 + ty + i * 8;
        t[ty + i * 8][tx] = W[(size_t)y * 512 + x];
    }
    __syncthreads();
    const int x2 = by * 32 + tx;                           // k
#pragma unroll
    for (int i = 0; i < 4; i++) {
        const int y2 = bx * 32 + ty + i * 8;               // n
        g_Wt_h[(size_t)y2 * 512 + x2] = __float2half_rn(t[tx][ty + i * 8]);
    }
}

// ---------------------------------------------------------------------------
// Kernel 0b: row_ptr from sorted edge_dst.
// ---------------------------------------------------------------------------
__global__ void rowptr_kernel(const int* __restrict__ edge_dst) {
    const int e = blockIdx.x * blockDim.x + threadIdx.x;
    if (e > N_EDGES) return;
    const int d_prev = (e == 0)       ? -1      : edge_dst[e - 1];
    const int d_cur  = (e == N_EDGES) ? N_NODES : edge_dst[e];
    for (int n = d_prev + 1; n <= d_cur; n++) g_rowptr[n] = e;
}

// ---------------------------------------------------------------------------
// Kernel 1: dropout, JAX partitionable threefry-2x32-20; fp16 output.
// keep <=> bits < 0xE6666600 (== 7549747<<9; exact integer form of u < 0.9f).
// 8 elements per thread.
// ---------------------------------------------------------------------------
__device__ __forceinline__ unsigned rotl32(unsigned x, int d) {
    return (x << d) | (x >> (32 - d));
}
__device__ __forceinline__ unsigned threefry_elem(unsigned i) {
    const unsigned ks0 = 0u, ks1 = 42u;
    const unsigned ks2 = ks0 ^ ks1 ^ 0x1BD11BDAu;
    unsigned x0 = 0u, x1 = i;
    x0 += ks0; x1 += ks1;
#define TF_ROUND(r) { x0 += x1; x1 = rotl32(x1, (r)); x1 ^= x0; }
    TF_ROUND(13) TF_ROUND(15) TF_ROUND(26) TF_ROUND(6)
    x0 += ks1; x1 += ks2 + 1u;
    TF_ROUND(17) TF_ROUND(29) TF_ROUND(16) TF_ROUND(24)
    x0 += ks2; x1 += ks0 + 2u;
    TF_ROUND(13) TF_ROUND(15) TF_ROUND(26) TF_ROUND(6)
    x0 += ks0; x1 += ks1 + 3u;
    TF_ROUND(17) TF_ROUND(29) TF_ROUND(16) TF_ROUND(24)
    x0 += ks1; x1 += ks2 + 4u;
    TF_ROUND(13) TF_ROUND(15) TF_ROUND(26) TF_ROUND(6)
    x0 += ks2; x1 += ks0 + 5u;
#undef TF_ROUND
    return x0 ^ x1;
}

__global__ void dropout_kernel(const float* __restrict__ x) {
    const unsigned base = (blockIdx.x * blockDim.x + threadIdx.x) * 8u;
    if (base >= (unsigned)N_ELEMS) return;
    const float4 va = __ldcs(reinterpret_cast<const float4*>(x + base));
    const float4 vb = __ldcs(reinterpret_cast<const float4*>(x + base + 4));
    const float inv_keep = 1.0f / 0.9f;
    const unsigned THR = 0xE6666600u;

    float o[8];
    const float vi[8] = { va.x, va.y, va.z, va.w, vb.x, vb.y, vb.z, vb.w };
#pragma unroll
    for (int j = 0; j < 8; j++) {
        const unsigned bj = threefry_elem(base + (unsigned)j);
        o[j] = (bj < THR) ? vi[j] * inv_keep : 0.0f;
    }
    uint4 pack;
    const __half2 h0 = __floats2half2_rn(o[0], o[1]);
    const __half2 h1 = __floats2half2_rn(o[2], o[3]);
    const __half2 h2 = __floats2half2_rn(o[4], o[5]);
    const __half2 h3 = __floats2half2_rn(o[6], o[7]);
    pack.x = *reinterpret_cast<const uint32_t*>(&h0);
    pack.y = *reinterpret_cast<const uint32_t*>(&h1);
    pack.z = *reinterpret_cast<const uint32_t*>(&h2);
    pack.w = *reinterpret_cast<const uint32_t*>(&h3);
    *reinterpret_cast<uint4*>(g_xd_h + base) = pack;
}

// ---------------------------------------------------------------------------
// Kernel 2: segment-sum aggregation over fp16 xd; fp32 accumulate; fp16 out.
// Edge list staged through smem: gather addresses come from LDS (29 cyc)
// instead of LDG (~300 cyc), so gathers issue back-to-back (high MLP).
// ---------------------------------------------------------------------------
__global__ void agg_kernel(const float* __restrict__ edge_w,
                           const int*   __restrict__ edge_src) {
    __shared__ float sw[128];
    __shared__ int   ss[128];

    const int node = blockIdx.x;
    const int start = g_rowptr[node];
    const int end   = g_rowptr[node + 1];

    const int f = threadIdx.x;  // 0..127, owns feats [4f, 4f+4)
    float4 acc = make_float4(0.f, 0.f, 0.f, 0.f);

#pragma unroll 1
    for (int c0 = start; c0 < end; c0 += 128) {
        const int cnt = min(end - c0, 128);
        __syncthreads();                       // protect sw/ss from prior chunk
        if (f < cnt) { sw[f] = edge_w[c0 + f]; ss[f] = edge_src[c0 + f]; }
        __syncthreads();

        int e = 0;
#pragma unroll 1
        for (; e + 4 <= cnt; e += 4) {
            const float w0 = sw[e + 0], w1 = sw[e + 1];
            const float w2 = sw[e + 2], w3 = sw[e + 3];
            const int   s0 = ss[e + 0], s1 = ss[e + 1];
            const int   s2 = ss[e + 2], s3 = ss[e + 3];
            const uint2 r0 = reinterpret_cast<const uint2*>(g_xd_h + (size_t)s0 * FEATS)[f];
            const uint2 r1 = reinterpret_cast<const uint2*>(g_xd_h + (size_t)s1 * FEATS)[f];
            const uint2 r2 = reinterpret_cast<const uint2*>(g_xd_h + (size_t)s2 * FEATS)[f];
            const uint2 r3 = reinterpret_cast<const uint2*>(g_xd_h + (size_t)s3 * FEATS)[f];
#define ACC_EDGE(rr, ww) { \
            const float2 lo = __half22float2(*reinterpret_cast<const __half2*>(&(rr).x)); \
            const float2 hi = __half22float2(*reinterpret_cast<const __half2*>(&(rr).y)); \
            acc.x += (ww) * lo.x; acc.y += (ww) * lo.y; \
            acc.z += (ww) * hi.x; acc.w += (ww) * hi.y; }
            ACC_EDGE(r0, w0) ACC_EDGE(r1, w1) ACC_EDGE(r2, w2) ACC_EDGE(r3, w3)
        }
#pragma unroll 1
        for (; e < cnt; e++) {
            const float w = sw[e];
            const int   s = ss[e];
            const uint2 rr = reinterpret_cast<const uint2*>(g_xd_h + (size_t)s * FEATS)[f];
            ACC_EDGE(rr, w)
        }
#undef ACC_EDGE
    }
    const __half2 h01 = __floats2half2_rn(acc.x, acc.y);
    const __half2 h23 = __floats2half2_rn(acc.z, acc.w);
    uint2 pack;
    pack.x = *reinterpret_cast<const uint32_t*>(&h01);
    pack.y = *reinterpret_cast<const uint32_t*>(&h23);
    __stcs(reinterpret_cast<uint2*>(g_agg_h + (size_t)node * FEATS) + f, pack);
}

// ---------------------------------------------------------------------------
// Kernel 3: fp16 mma.sync m16n8k16 GEMM, fp32 accum, ldmatrix fragments.
// 128x128 CTA tile, 8 warps (64x32 warp tiles), BK=64 halves, 2-stage
// cp.async, smem rows 144 B. (R11 measured-best configuration.)
// ---------------------------------------------------------------------------
#define BKH 64                          // halves per K chunk
#define LDH 72                          // padded halves per row (144 B)
#define STAGE_H (128 * LDH)             // halves per stage per matrix
#define GEMM_SMEM_BYTES (4 * STAGE_H * 2)   // A0,A1,B0,B1 = 73728 B

__global__ void __launch_bounds__(256, 2)
gemm_mma_kernel(const float* __restrict__ bias, float* __restrict__ out) {
    extern __shared__ __half smh[];
    __half* Asm = smh;                  // [2][128][LDH]
    __half* Bsm = smh + 2 * STAGE_H;    // [2][128][LDH]

    const int tid   = threadIdx.x;
    const int wid   = tid >> 5;
    const int lane  = tid & 31;
    const int warpM = wid & 1;          // M offset 0/64
    const int warpN = wid >> 1;         // 0..3 -> N offset 0/32/64/96
    const int m0 = blockIdx.y * 128;
    const int n0 = blockIdx.x * 128;

    const uint32_t aBase = smem_u32(Asm);
    const uint32_t bBase = smem_u32(Bsm);
    const uint32_t stageBytes = STAGE_H * 2;

    const int rA   = warpM * 64 + (lane & 15);
    const int kAh  = (lane & 16) ? 8 : 0;
    const uint32_t aLane = (uint32_t)(rA * LDH + kAh) * 2;
    const int rB   = warpN * 32 + (lane & 7) + ((lane & 16) >> 1);
    const int kBh  = (lane & 8) ? 8 : 0;
    const uint32_t bLane = (uint32_t)(rB * LDH + kBh) * 2;

    float acc[4][4][4];
#pragma unroll
    for (int i = 0; i < 4; i++)
#pragma unroll
        for (int j = 0; j < 4; j++)
#pragma unroll
            for (int r = 0; r < 4; r++) acc[i][j][r] = 0.f;

    auto load_tile = [&](int s, int k0) {
#pragma unroll
        for (int it = 0; it < 4; it++) {
            const int idx = it * 256 + tid;            // 0..1023
            const int row = idx >> 3, seg = idx & 7;
            cp_async16(aBase + s * stageBytes + row * 144 + seg * 16,
                       g_agg_h + (size_t)(m0 + row) * 512 + k0 + seg * 8);
        }
#pragma unroll
        for (int it = 0; it < 4; it++) {
            const int idx = it * 256 + tid;
            const int row = idx >> 3, seg = idx & 7;
            cp_async16(bBase + s * stageBytes + row * 144 + seg * 16,
                       g_Wt_h + (size_t)(n0 + row) * 512 + k0 + seg * 8);
        }
        cp_commit();
    };

    load_tile(0, 0);

    for (int c = 0; c < 8; c++) {
        const int s = c & 1;
        cp_wait<0>();
        __syncthreads();
        if (c + 1 < 8) load_tile(s ^ 1, (c + 1) * BKH);   // overlaps mma below

        const uint32_t aStage = aBase + s * stageBytes + aLane;
        const uint32_t bStage = bBase + s * stageBytes + bLane;
#pragma unroll
        for (int kk = 0; kk < 4; kk++) {
            const uint32_t kOff = kk * 32;                // 16 halves = 32 B
            uint32_t af[4][4];
#pragma unroll
            for (int mt = 0; mt < 4; mt++)
                ldsm_x4(af[mt][0], af[mt][1], af[mt][2], af[mt][3],
                        aStage + (uint32_t)(mt * 16 * LDH) * 2 + kOff);
            uint32_t bf[4][2];
#pragma unroll
            for (int ntp = 0; ntp < 2; ntp++)
                ldsm_x4(bf[2 * ntp][0], bf[2 * ntp][1],
                        bf[2 * ntp + 1][0], bf[2 * ntp + 1][1],
                        bStage + (uint32_t)(ntp * 16 * LDH) * 2 + kOff);
#pragma unroll
            for (int mt = 0; mt < 4; mt++)
#pragma unroll
                for (int nt = 0; nt < 4; nt++)
                    mma_f16(acc[mt][nt], af[mt], bf[nt]);
        }
    }

    const int qrow = lane >> 2;
    const int qcol = lane & 3;

    // epilogue: bias + relu, streaming stores
#pragma unroll
    for (int mt = 0; mt < 4; mt++) {
        const int row0 = m0 + warpM * 64 + mt * 16 + qrow;
        const int row1 = row0 + 8;
#pragma unroll
        for (int nt = 0; nt < 4; nt++) {
            const int col = n0 + warpN * 32 + nt * 8 + 2 * qcol;
            const float b0 = __ldg(bias + col);
            const float b1 = __ldg(bias + col + 1);
            if (row0 < N_NODES) {
                float2 o;
                o.x = fmaxf(acc[mt][nt][0] + b0, 0.f);
                o.y = fmaxf(acc[mt][nt][1] + b1, 0.f);
                __stcs(reinterpret_cast<float2*>(out + (size_t)row0 * 512 + col), o);
            }
            if (row1 < N_NODES) {
                float2 o;
                o.x = fmaxf(acc[mt][nt][2] + b0, 0.f);
                o.y = fmaxf(acc[mt][nt][3] + b1, 0.f);
                __stcs(reinterpret_cast<float2*>(out + (size_t)row1 * 512 + col), o);
            }
        }
    }
}

// ---------------------------------------------------------------------------
// Launch: serial core (measured optimum); aux forked under dropout (free).
// ---------------------------------------------------------------------------
extern "C" void kernel_launch(void* const* d_in, const int* in_sizes, int n_in,
                              void* d_out, int out_size) {
    const float* x        = (const float*)d_in[0];
    const float* edge_w   = (const float*)d_in[1];
    const float* W        = (const float*)d_in[2];
    const float* b        = (const float*)d_in[3];
    const int*   edge_src = (const int*)  d_in[4];
    const int*   edge_dst = (const int*)  d_in[5];
    float* out = (float*)d_out;

    static cudaStream_t s1 = nullptr;
    static cudaEvent_t evStart, evAux;
    if (s1 == nullptr) {
        cudaStreamCreateWithFlags(&s1, cudaStreamNonBlocking);
        cudaEventCreateWithFlags(&evStart, cudaEventDisableTiming);
        cudaEventCreateWithFlags(&evAux,   cudaEventDisableTiming);
        cudaFuncSetAttribute(gemm_mma_kernel,
                             cudaFuncAttributeMaxDynamicSharedMemorySize,
                             GEMM_SMEM_BYTES);
    }

    cudaEventRecord(evStart, 0);
    cudaStreamWaitEvent(s1, evStart, 0);
    transpose_W_kernel<<<dim3(16, 16), dim3(32, 8), 0, s1>>>(W);
    rowptr_kernel<<<(N_EDGES + 256) / 256, 256, 0, s1>>>(edge_dst);
    cudaEventRecord(evAux, s1);

    dropout_kernel<<<(N_ELEMS / 8 + 255) / 256, 256, 0, 0>>>(x);

    cudaStreamWaitEvent(0, evAux, 0);
    agg_kernel<<<N_NODES, 128, 0, 0>>>(edge_w, edge_src);
    gemm_mma_kernel<<<dim3(4, M_TILES), 256, GEMM_SMEM_BYTES, 0>>>(b, out);
}